// round 12
// baseline (speedup 1.0000x reference)
#include <cuda_runtime.h>
#include <cuda_bf16.h>
#include <math.h>
#include <stdint.h>

#define N_B 16
#define D 128
#define L0 2048
#define L1 1024
#define H 384
#define CHUNK 64
#define CH0 (L0/CHUNK)   // 32
#define CH1 (L1/CHUNK)   // 16

#define BM 128
#define NBLK0 (N_B*(L0/BM))  // 256
#define NBLK1 (N_B*(L1/BM))  // 128
#define OROW 129
#define OUTROW 136
#define NT_GEMM 512

// Dynamic smem layout (bytes)
#define SO_AM   64                   // 128 ints
#define SO_DV   576                  // 128 floats
#define SO_BS   1088                 // 128 floats
#define SO_AF   4096                 // A fragments hi (32KB) + lo (32KB)
#define SO_BF   (SO_AF + 65536)      // B fragments hi (32KB) + lo (32KB)
#define SO_OBC  (SO_BF + 65536)      // bias+corr [128][OROW] f32
#define SMEM_TC (SO_OBC + BM * OROW * 4)   // 201216 bytes

// Scratch (device globals; no allocation allowed)
__device__ float g_pm1[2][N_B][CH0][D];
__device__ float g_pm2[2][N_B][CH0][D];
__device__ int   g_pam[2][N_B][CH0][D];
__device__ float g_top1[2][N_B][D];
__device__ float g_delta[2][N_B][D];
__device__ int   g_amax[2][N_B][D];
__device__ float g_base[2][N_B][D];

// ---------------------------------------------------------------------------
__device__ __forceinline__ void mma_bf16(float* d, const uint32_t* a, const uint32_t* b) {
    asm volatile(
        "mma.sync.aligned.m16n8k16.row.col.f32.bf16.bf16.f32 "
        "{%0,%1,%2,%3}, {%4,%5,%6,%7}, {%8,%9}, {%0,%1,%2,%3};\n"
        : "+f"(d[0]), "+f"(d[1]), "+f"(d[2]), "+f"(d[3])
        : "r"(a[0]), "r"(a[1]), "r"(a[2]), "r"(a[3]), "r"(b[0]), "r"(b[1]));
}

// hi/lo bf16x2 split of a float2 (exact residual split)
__device__ __forceinline__ void split2(float2 v, uint32_t& hi, uint32_t& lo) {
    __nv_bfloat162 h = __float22bfloat162_rn(v);
    float2 hf = __bfloat1622float2(h);
    __nv_bfloat162 l = __float22bfloat162_rn(make_float2(v.x - hf.x, v.y - hf.y));
    hi = *(uint32_t*)&h;
    lo = *(uint32_t*)&l;
}

// ---------------------------------------------------------------------------
// Stage 1: per-chunk top2 + argmax; float4 per thread (4 d's), MLP-4 batches.
// Block 128 thr = 4 chunks; grid (12, 16) covers 48 chunks (32 g0 + 16 g1).
// ---------------------------------------------------------------------------
__global__ void reduce_partial(const float* __restrict__ x0,
                               const float* __restrict__ x1) {
    int n = blockIdx.y;
    int cc = blockIdx.x * 4 + (threadIdx.x >> 5);
    int d4 = (threadIdx.x & 31) * 4;
    int g, chunk, L;
    const float* x;
    if (cc < CH0) { g = 0; chunk = cc;       L = L0; x = x0; }
    else          { g = 1; chunk = cc - CH0; L = L1; x = x1; }
    const float* p = x + ((size_t)n * L + (size_t)chunk * CHUNK) * D + d4;

    float m1[4], m2[4];
    int am[4];
    #pragma unroll
    for (int j = 0; j < 4; ++j) { m1[j] = -INFINITY; m2[j] = -INFINITY; am[j] = 0; }

    for (int r0 = 0; r0 < CHUNK; r0 += 4) {
        float4 v[4];
        #pragma unroll
        for (int u = 0; u < 4; ++u)
            v[u] = *(const float4*)(p + (size_t)(r0 + u) * D);
        #pragma unroll
        for (int u = 0; u < 4; ++u) {
            float a[4] = {v[u].x, v[u].y, v[u].z, v[u].w};
            int row = chunk * CHUNK + r0 + u;
            #pragma unroll
            for (int j = 0; j < 4; ++j) {
                if (a[j] > m1[j]) { m2[j] = m1[j]; m1[j] = a[j]; am[j] = row; }
                else if (a[j] > m2[j]) { m2[j] = a[j]; }
            }
        }
    }
    *(float4*)&g_pm1[g][n][chunk][d4] = make_float4(m1[0], m1[1], m1[2], m1[3]);
    *(float4*)&g_pm2[g][n][chunk][d4] = make_float4(m2[0], m2[1], m2[2], m2[3]);
    *(int4*)&g_pam[g][n][chunk][d4]   = make_int4(am[0], am[1], am[2], am[3]);
}

// ---------------------------------------------------------------------------
// Stage 2 (fused): final merge for both groups + per-(g,n,o) base bias.
// One block per n, 256 threads (8 warps).
// ---------------------------------------------------------------------------
__global__ void finalize_kernel(const float* __restrict__ W0, const float* __restrict__ b0,
                                const float* __restrict__ W1, const float* __restrict__ b1) {
    int n = blockIdx.x;
    int tid = threadIdx.x;
    __shared__ float tv[2 * D];

    {   // merge partials: tid<128 -> g0, else g1
        int g = tid >> 7, d = tid & 127;
        int CH = g ? CH1 : CH0;
        float m1 = -INFINITY, m2 = -INFINITY;
        int am = 0;
        for (int c0 = 0; c0 < CH; c0 += 4) {
            float p1[4], p2[4]; int pa[4];
            #pragma unroll
            for (int u = 0; u < 4; ++u) {
                p1[u] = g_pm1[g][n][c0 + u][d];
                p2[u] = g_pm2[g][n][c0 + u][d];
                pa[u] = g_pam[g][n][c0 + u][d];
            }
            #pragma unroll
            for (int u = 0; u < 4; ++u) {
                if (p1[u] > m1) { m2 = fmaxf(m1, p2[u]); m1 = p1[u]; am = pa[u]; }
                else            { m2 = fmaxf(m2, p1[u]); }
            }
        }
        g_top1[g][n][d]  = m1;
        g_delta[g][n][d] = m2 - m1;
        g_amax[g][n][d]  = am;
        tv[g * D + d] = m1;
    }
    __syncthreads();

    // base: 8 warps, each warp 16 o's per group-half; lane over dd (coalesced)
    int lane = tid & 31, w = tid >> 5;
    #pragma unroll
    for (int gg = 0; gg < 2; ++gg) {
        const float* W = gg ? W1 : W0;
        const float* b = gg ? b1 : b0;
        #pragma unroll
        for (int oo = 0; oo < 16; ++oo) {
            int o = w + 8 * oo;
            const float* wr = W + (size_t)o * H + D;   // cols 128..383
            float s = 0.0f;
            #pragma unroll
            for (int c = 0; c < 8; ++c) { int dd = lane + 32 * c; s += tv[dd] * wr[dd]; }
            #pragma unroll
            for (int off = 16; off; off >>= 1) s += __shfl_down_sync(0xffffffffu, s, off);
            if (lane == 0) g_base[gg][n][o] = s + b[o];
        }
    }
}

// ---------------------------------------------------------------------------
// Stage 3: HMMA GEMM. Conflict-free vectorized fragment staging; per-kstep
// shared-fragment 3-pass (hh, hl, lh). 16 warps: 4Mx4N grid, 32x32 warp tile.
// ---------------------------------------------------------------------------
__global__ void __launch_bounds__(NT_GEMM, 1)
gemm_mma(const float* __restrict__ x0, const float* __restrict__ x1,
         const float* __restrict__ W0, const float* __restrict__ W1,
         float* __restrict__ yout) {
    extern __shared__ char sm[];

    int bid = blockIdx.x;
    int g, n, t, L, wboff;
    const float* x; const float* W; float* y;
    if (bid < NBLK0) {
        g = 0; n = bid >> 4; t = bid & 15; L = L0; wboff = D;
        x = x0; W = W0; y = yout;
    } else {
        int b2 = bid - NBLK0;
        g = 1; n = b2 >> 3; t = b2 & 7; L = L1; wboff = 2 * D;
        x = x1; W = W1; y = yout + (size_t)N_B * L0 * D;
    }
    int row0 = t * BM;
    int tid = threadIdx.x, wid = tid >> 5, lane = tid & 31;

    int*      s_am = (int*)(sm + SO_AM);
    float*    s_dv = (float*)(sm + SO_DV);
    float*    s_bs = (float*)(sm + SO_BS);
    uint32_t* AF   = (uint32_t*)(sm + SO_AF);   // hi; lo at +8192 words
    uint32_t* BF   = (uint32_t*)(sm + SO_BF);   // hi; lo at +8192 words
    float*    Obc  = (float*)(sm + SO_OBC);

    if (tid < D) {
        s_am[tid] = g_amax[g][n][tid];
        s_dv[tid] = g_delta[g][n][tid];
        s_bs[tid] = g_base[g][n][tid];
    }

    // ---- Stage A: each thread fills one full fragment uint4 (hi and lo).
    // Slot: tile = kstep*8 + mtile (rows mtile*16..+15), lane ln.
    // reg order {r0/k0, r0+8/k0, r0/k0+8, r0+8/k0+8} matches m16n8k16 A frag.
    const float* xb = x + ((size_t)n * L + row0) * D;
    #pragma unroll
    for (int it = 0; it < 4; ++it) {
        int slot = tid + NT_GEMM * it;       // 2048 slots
        int tile = slot >> 5, ln = slot & 31;
        int kstep = tile >> 3, mt = tile & 7;
        int r0 = mt * 16 + (ln >> 2), t4 = ln & 3;
        int kb = kstep * 16 + 2 * t4;
        const float* base = xb + (size_t)r0 * D + kb;
        float2 v00 = *(const float2*)(base);
        float2 v10 = *(const float2*)(base + 8 * D);
        float2 v01 = *(const float2*)(base + 8);
        float2 v11 = *(const float2*)(base + 8 * D + 8);
        uint32_t h0, l0, h1, l1, h2, l2, h3, l3;
        split2(v00, h0, l0); split2(v10, h1, l1);
        split2(v01, h2, l2); split2(v11, h3, l3);
        int widx = tile * 128 + ln * 4;
        *(uint4*)(AF + widx)        = make_uint4(h0, h1, h2, h3);
        *(uint4*)(AF + 8192 + widx) = make_uint4(l0, l1, l2, l3);
    }
    // ---- Stage B: one uint2 fragment per thread (hi and lo).
    // tile = kstep*16 + ntile (cols ntile*8..+7); regs {k0, k0+8}.
    #pragma unroll
    for (int it = 0; it < 8; ++it) {
        int slot = tid + NT_GEMM * it;       // 4096 slots
        int tile = slot >> 5, ln = slot & 31;
        int kstep = tile >> 4, nt = tile & 15;
        int o = nt * 8 + (ln >> 2), t4 = ln & 3;
        int kb = kstep * 16 + 2 * t4;
        const float* base = W + (size_t)o * H + kb;
        float2 v0 = *(const float2*)(base);
        float2 v1 = *(const float2*)(base + 8);
        uint32_t h0, lo0, h1, lo1;
        split2(v0, h0, lo0); split2(v1, h1, lo1);
        int widx = tile * 64 + ln * 2;
        *(uint2*)(BF + widx)        = make_uint2(h0, h1);
        *(uint2*)(BF + 8192 + widx) = make_uint2(lo0, lo1);
    }
    __syncthreads();

    // ---- Bias + sparse LOO corrections into Obc (disjoint smem region)
    for (int i = tid; i < BM * D; i += NT_GEMM) {
        int r = i >> 7, c = i & 127;
        Obc[r * OROW + c] = s_bs[c];
    }
    __syncthreads();
    for (int d = 0; d < D; ++d) {
        int lr = s_am[d] - row0;
        if ((unsigned)lr < (unsigned)BM && (lr & 15) == wid) {   // warp-owned rows
            float dv = s_dv[d];
            const float* wr = W + wboff + d;
            #pragma unroll
            for (int c = lane; c < D; c += 32)
                Obc[lr * OROW + c] += dv * wr[(size_t)c * H];
        }
    }

    // ---- MMA mainloop: 8 ksteps; per kstep load hi+lo frags once, 3 passes.
    int warp_m = wid & 3, warp_n = wid >> 2;
    float acc[2][4][4];
    #pragma unroll
    for (int mt = 0; mt < 2; ++mt)
        #pragma unroll
        for (int nt = 0; nt < 4; ++nt)
            #pragma unroll
            for (int q = 0; q < 4; ++q) acc[mt][nt][q] = 0.0f;

    #pragma unroll
    for (int ks = 0; ks < 8; ++ks) {
        uint32_t ah[2][4], al[2][4], bh[4][2], bl[4][2];
        #pragma unroll
        for (int mt = 0; mt < 2; ++mt) {
            const uint32_t* ab = AF + ((ks << 3) + (warp_m << 1) + mt) * 128;
            uint4 vh = ((const uint4*)ab)[lane];
            uint4 vl = ((const uint4*)(ab + 8192))[lane];
            ah[mt][0] = vh.x; ah[mt][1] = vh.y; ah[mt][2] = vh.z; ah[mt][3] = vh.w;
            al[mt][0] = vl.x; al[mt][1] = vl.y; al[mt][2] = vl.z; al[mt][3] = vl.w;
        }
        #pragma unroll
        for (int nt = 0; nt < 4; ++nt) {
            const uint32_t* bb = BF + ((ks << 4) + (warp_n << 2) + nt) * 64;
            uint2 wh = ((const uint2*)bb)[lane];
            uint2 wl = ((const uint2*)(bb + 8192))[lane];
            bh[nt][0] = wh.x; bh[nt][1] = wh.y;
            bl[nt][0] = wl.x; bl[nt][1] = wl.y;
        }
        #pragma unroll
        for (int mt = 0; mt < 2; ++mt)
            #pragma unroll
            for (int nt = 0; nt < 4; ++nt) {
                mma_bf16(acc[mt][nt], ah[mt], bh[nt]);
                mma_bf16(acc[mt][nt], ah[mt], bl[nt]);
                mma_bf16(acc[mt][nt], al[mt], bh[nt]);
            }
    }

    // ---- Restage accumulators through smem (reuse AF/BF region), coalesced out
    __syncthreads();                     // all warps done reading AF/BF
    float* Out = (float*)(sm + SO_AF);   // [128][OUTROW]
    int gq = lane >> 2, t4q = lane & 3;
    #pragma unroll
    for (int mt = 0; mt < 2; ++mt) {
        int rbase = warp_m * 32 + mt * 16 + gq;
        #pragma unroll
        for (int nt = 0; nt < 4; ++nt) {
            int c = warp_n * 32 + nt * 8 + 2 * t4q;
            *(float2*)&Out[rbase * OUTROW + c]       = make_float2(acc[mt][nt][0], acc[mt][nt][1]);
            *(float2*)&Out[(rbase + 8) * OUTROW + c] = make_float2(acc[mt][nt][2], acc[mt][nt][3]);
        }
    }
    __syncthreads();

    float* yb = y + ((size_t)n * L + row0) * D;
    #pragma unroll
    for (int it = 0; it < 8; ++it) {
        int q = it * NT_GEMM + tid;
        int r = q >> 5, c4 = (q & 31) * 4;
        float4 v = *(const float4*)&Out[r * OUTROW + c4];
        v.x += Obc[r * OROW + c4];
        v.y += Obc[r * OROW + c4 + 1];
        v.z += Obc[r * OROW + c4 + 2];
        v.w += Obc[r * OROW + c4 + 3];
        *(float4*)&yb[(size_t)r * D + c4] = v;
    }
}

// ---------------------------------------------------------------------------
extern "C" void kernel_launch(void* const* d_in, const int* in_sizes, int n_in,
                              void* d_out, int out_size) {
    (void)in_sizes; (void)n_in; (void)out_size;
    const float* x0 = (const float*)d_in[0];
    const float* x1 = (const float*)d_in[1];
    const float* W0 = (const float*)d_in[2];
    const float* b0 = (const float*)d_in[3];
    const float* W1 = (const float*)d_in[4];
    const float* b1 = (const float*)d_in[5];
    float* y = (float*)d_out;

    cudaFuncSetAttribute(gemm_mma, cudaFuncAttributeMaxDynamicSharedMemorySize, SMEM_TC);

    reduce_partial<<<dim3((CH0 + CH1) / 4, N_B), 128>>>(x0, x1);
    finalize_kernel<<<N_B, 256>>>(W0, b0, W1, b1);
    gemm_mma<<<NBLK0 + NBLK1, NT_GEMM, SMEM_TC>>>(x0, x1, W0, W1, y);
}

// round 13
// speedup vs baseline: 1.0409x; 1.0409x over previous
#include <cuda_runtime.h>
#include <cuda_bf16.h>
#include <math.h>
#include <stdint.h>

#define N_B 16
#define D 128
#define L0 2048
#define L1 1024
#define H 384
#define CHUNK 32
#define CH0 (L0/CHUNK)   // 64
#define CH1 (L1/CHUNK)   // 32

#define BM 64
#define NBLK0 (N_B*(L0/BM))  // 512
#define NBLK1 (N_B*(L1/BM))  // 256
#define OROW 128
#define OUTROW 136
#define NT_GEMM 256

// Dynamic smem layout (bytes). Total 102400 -> 2 blocks/SM.
#define SO_AM   64                    // 128 ints
#define SO_DV   576                   // 128 floats
#define SO_BS   1088                  // 128 floats
#define SO_AF   4096                  // A frags: hi 16KB + lo 16KB
#define SO_BF   36864                 // B frags: hi 32KB + lo 32KB
#define SO_OBC  69632                 // (epilogue overlay) bias+corr [64][128] f32
#define SMEM_TC 102400
#define A_LO_W  4096                  // word offset of A lo
#define B_LO_W  8192                  // word offset of B lo

// Scratch (device globals; no allocation allowed)
__device__ float g_pm1[2][N_B][CH0][D];
__device__ float g_pm2[2][N_B][CH0][D];
__device__ int   g_pam[2][N_B][CH0][D];
__device__ float g_top1[2][N_B][D];
__device__ float g_delta[2][N_B][D];
__device__ int   g_amax[2][N_B][D];
__device__ float g_base[2][N_B][D];

// ---------------------------------------------------------------------------
__device__ __forceinline__ void mma_bf16(float* d, const uint32_t* a, const uint32_t* b) {
    asm volatile(
        "mma.sync.aligned.m16n8k16.row.col.f32.bf16.bf16.f32 "
        "{%0,%1,%2,%3}, {%4,%5,%6,%7}, {%8,%9}, {%0,%1,%2,%3};\n"
        : "+f"(d[0]), "+f"(d[1]), "+f"(d[2]), "+f"(d[3])
        : "r"(a[0]), "r"(a[1]), "r"(a[2]), "r"(a[3]), "r"(b[0]), "r"(b[1]));
}

// hi/lo bf16x2 split of a float2 (exact residual split)
__device__ __forceinline__ void split2(float2 v, uint32_t& hi, uint32_t& lo) {
    __nv_bfloat162 h = __float22bfloat162_rn(v);
    float2 hf = __bfloat1622float2(h);
    __nv_bfloat162 l = __float22bfloat162_rn(make_float2(v.x - hf.x, v.y - hf.y));
    hi = *(uint32_t*)&h;
    lo = *(uint32_t*)&l;
}

// ---------------------------------------------------------------------------
// Stage 1: per-chunk (32 rows) top2 + argmax. 1536 blocks x 128 thr, 1 d/thread.
// ---------------------------------------------------------------------------
__global__ void reduce_partial(const float* __restrict__ x0,
                               const float* __restrict__ x1) {
    int n = blockIdx.y, c = blockIdx.x, d = threadIdx.x;
    int g, chunk, L;
    const float* x;
    if (c < CH0) { g = 0; chunk = c;       L = L0; x = x0; }
    else         { g = 1; chunk = c - CH0; L = L1; x = x1; }
    const float* p = x + ((size_t)n * L + (size_t)chunk * CHUNK) * D + d;
    float m1 = -INFINITY, m2 = -INFINITY;
    int am = 0;
    #pragma unroll
    for (int r0 = 0; r0 < CHUNK; r0 += 8) {
        float v[8];
        #pragma unroll
        for (int u = 0; u < 8; ++u) v[u] = p[(size_t)(r0 + u) * D];
        #pragma unroll
        for (int u = 0; u < 8; ++u) {
            if (v[u] > m1) { m2 = m1; m1 = v[u]; am = chunk * CHUNK + r0 + u; }
            else if (v[u] > m2) { m2 = v[u]; }
        }
    }
    g_pm1[g][n][chunk][d] = m1;
    g_pm2[g][n][chunk][d] = m2;
    g_pam[g][n][chunk][d] = am;
}

// ---------------------------------------------------------------------------
// Stage 2: merge partials -> top1 / (top2-top1) / argmax. Grid (16, 2), 128 thr.
// ---------------------------------------------------------------------------
__global__ void merge_kernel() {
    int n = blockIdx.x, g = blockIdx.y, d = threadIdx.x;
    int CH = g ? CH1 : CH0;
    float m1 = -INFINITY, m2 = -INFINITY;
    int am = 0;
    for (int c0 = 0; c0 < CH; c0 += 4) {
        float p1[4], p2[4]; int pa[4];
        #pragma unroll
        for (int u = 0; u < 4; ++u) {
            p1[u] = g_pm1[g][n][c0 + u][d];
            p2[u] = g_pm2[g][n][c0 + u][d];
            pa[u] = g_pam[g][n][c0 + u][d];
        }
        #pragma unroll
        for (int u = 0; u < 4; ++u) {
            if (p1[u] > m1) { m2 = fmaxf(m1, p2[u]); m1 = p1[u]; am = pa[u]; }
            else            { m2 = fmaxf(m2, p1[u]); }
        }
    }
    g_top1[g][n][d]  = m1;
    g_delta[g][n][d] = m2 - m1;
    g_amax[g][n][d]  = am;
}

// ---------------------------------------------------------------------------
// Stage 3: base bias. Grid (16, 2), 512 thr: 16 warps x 8 o's, lanes over dd.
//   base[g][n][o] = b[o] + top1_x0·W[o,128:256] + top1_x1·W[o,256:384]
// ---------------------------------------------------------------------------
__global__ void base_kernel(const float* __restrict__ W0, const float* __restrict__ b0,
                            const float* __restrict__ W1, const float* __restrict__ b1) {
    int n = blockIdx.x, g = blockIdx.y;
    const float* W = g ? W1 : W0;
    const float* b = g ? b1 : b0;
    int tid = threadIdx.x;
    __shared__ float tv[2 * D];
    if (tid < D)          tv[tid] = g_top1[0][n][tid];
    else if (tid < 2 * D) tv[tid] = g_top1[1][n][tid - D];
    __syncthreads();
    int lane = tid & 31, w = tid >> 5;   // 16 warps
    #pragma unroll
    for (int oo = 0; oo < 8; ++oo) {
        int o = w + 16 * oo;
        const float* wr = W + (size_t)o * H + D;   // cols 128..383
        float s = 0.0f;
        #pragma unroll
        for (int c = 0; c < 8; ++c) { int dd = lane + 32 * c; s += tv[dd] * wr[dd]; }
        #pragma unroll
        for (int off = 16; off; off >>= 1) s += __shfl_down_sync(0xffffffffu, s, off);
        if (lane == 0) g_base[g][n][o] = s + b[o];
    }
}

// ---------------------------------------------------------------------------
// Stage 4: HMMA GEMM, 64x128 block tile, 100KB smem -> 2 blocks/SM.
// 8 warps: 2(M) x 4(N), warp tile 32x32. bf16 hi/lo 3-pass, pass-major order.
// ---------------------------------------------------------------------------
__global__ void __launch_bounds__(NT_GEMM, 2)
gemm_mma(const float* __restrict__ x0, const float* __restrict__ x1,
         const float* __restrict__ W0, const float* __restrict__ W1,
         float* __restrict__ yout) {
    extern __shared__ char sm[];

    int bid = blockIdx.x;
    int g, n, t, L, wboff;
    const float* x; const float* W; float* y;
    if (bid < NBLK0) {
        g = 0; n = bid >> 5; t = bid & 31; L = L0; wboff = D;
        x = x0; W = W0; y = yout;
    } else {
        int b2 = bid - NBLK0;
        g = 1; n = b2 >> 4; t = b2 & 15; L = L1; wboff = 2 * D;
        x = x1; W = W1; y = yout + (size_t)N_B * L0 * D;
    }
    int row0 = t * BM;
    int tid = threadIdx.x, wid = tid >> 5, lane = tid & 31;

    int*      s_am = (int*)(sm + SO_AM);
    float*    s_dv = (float*)(sm + SO_DV);
    float*    s_bs = (float*)(sm + SO_BS);
    uint32_t* AF   = (uint32_t*)(sm + SO_AF);
    uint32_t* BF   = (uint32_t*)(sm + SO_BF);

    if (tid < D) {
        s_am[tid] = g_amax[g][n][tid];
        s_dv[tid] = g_delta[g][n][tid];
        s_bs[tid] = g_base[g][n][tid];
    }

    // ---- Stage A (64 rows): 32 tiles (8ks x 4mt), full uint4 frag per thread.
    const float* xb = x + ((size_t)n * L + row0) * D;
    #pragma unroll
    for (int it = 0; it < 4; ++it) {
        int slot = tid + NT_GEMM * it;       // 1024 slots
        int tile = slot >> 5, ln = slot & 31;
        int ks = tile >> 2, mt = tile & 3;
        int r0 = mt * 16 + (ln >> 2), t4 = ln & 3;
        int kb = ks * 16 + 2 * t4;
        const float* base = xb + (size_t)r0 * D + kb;
        float2 v00 = *(const float2*)(base);
        float2 v10 = *(const float2*)(base + 8 * D);
        float2 v01 = *(const float2*)(base + 8);
        float2 v11 = *(const float2*)(base + 8 * D + 8);
        uint32_t h0, l0, h1, l1, h2, l2, h3, l3;
        split2(v00, h0, l0); split2(v10, h1, l1);
        split2(v01, h2, l2); split2(v11, h3, l3);
        int widx = tile * 128 + ln * 4;
        *(uint4*)(AF + widx)          = make_uint4(h0, h1, h2, h3);
        *(uint4*)(AF + A_LO_W + widx) = make_uint4(l0, l1, l2, l3);
    }
    // ---- Stage B (W[:, :128]): 128 tiles (8ks x 16nt), uint2 frag per thread.
    #pragma unroll
    for (int it = 0; it < 16; ++it) {
        int slot = tid + NT_GEMM * it;       // 4096 slots
        int tile = slot >> 5, ln = slot & 31;
        int ks = tile >> 4, nt = tile & 15;
        int o = nt * 8 + (ln >> 2), t4 = ln & 3;
        int kb = ks * 16 + 2 * t4;
        const float* base = W + (size_t)o * H + kb;
        float2 v0 = *(const float2*)(base);
        float2 v1 = *(const float2*)(base + 8);
        uint32_t h0, lo0, h1, lo1;
        split2(v0, h0, lo0); split2(v1, h1, lo1);
        int widx = tile * 64 + ln * 2;
        *(uint2*)(BF + widx)          = make_uint2(h0, h1);
        *(uint2*)(BF + B_LO_W + widx) = make_uint2(lo0, lo1);
    }
    __syncthreads();

    // ---- MMA mainloop: 8 ksteps; load frags once, 3 passes pass-major (ILP 8)
    int warp_m = wid & 1, warp_n = wid >> 1;
    float acc[2][4][4];
    #pragma unroll
    for (int mt = 0; mt < 2; ++mt)
        #pragma unroll
        for (int nt = 0; nt < 4; ++nt)
            #pragma unroll
            for (int q = 0; q < 4; ++q) acc[mt][nt][q] = 0.0f;

    #pragma unroll
    for (int ks = 0; ks < 8; ++ks) {
        uint32_t ah[2][4], al[2][4], bh[4][2], bl[4][2];
        #pragma unroll
        for (int mt = 0; mt < 2; ++mt) {
            const uint32_t* ab = AF + ((ks << 2) + (warp_m << 1) + mt) * 128;
            uint4 vh = ((const uint4*)ab)[lane];
            uint4 vl = ((const uint4*)(ab + A_LO_W))[lane];
            ah[mt][0] = vh.x; ah[mt][1] = vh.y; ah[mt][2] = vh.z; ah[mt][3] = vh.w;
            al[mt][0] = vl.x; al[mt][1] = vl.y; al[mt][2] = vl.z; al[mt][3] = vl.w;
        }
        #pragma unroll
        for (int nt = 0; nt < 4; ++nt) {
            const uint32_t* bb = BF + ((ks << 4) + (warp_n << 2) + nt) * 64;
            uint2 wh = ((const uint2*)bb)[lane];
            uint2 wl = ((const uint2*)(bb + B_LO_W))[lane];
            bh[nt][0] = wh.x; bh[nt][1] = wh.y;
            bl[nt][0] = wl.x; bl[nt][1] = wl.y;
        }
        #pragma unroll
        for (int mt = 0; mt < 2; ++mt)
            #pragma unroll
            for (int nt = 0; nt < 4; ++nt)
                mma_bf16(acc[mt][nt], ah[mt], bh[nt]);
        #pragma unroll
        for (int mt = 0; mt < 2; ++mt)
            #pragma unroll
            for (int nt = 0; nt < 4; ++nt)
                mma_bf16(acc[mt][nt], ah[mt], bl[nt]);
        #pragma unroll
        for (int mt = 0; mt < 2; ++mt)
            #pragma unroll
            for (int nt = 0; nt < 4; ++nt)
                mma_bf16(acc[mt][nt], al[mt], bh[nt]);
    }
    __syncthreads();   // frags dead; overlay Out/Obc

    // ---- Restage accumulators (Out overlays A region)
    float* Out = (float*)(sm + SO_AF);   // [64][OUTROW]
    float* Obc = (float*)(sm + SO_OBC);  // [64][OROW]
    int gq = lane >> 2, t4q = lane & 3;
    #pragma unroll
    for (int mt = 0; mt < 2; ++mt) {
        int rbase = warp_m * 32 + mt * 16 + gq;
        #pragma unroll
        for (int nt = 0; nt < 4; ++nt) {
            int c = warp_n * 32 + nt * 8 + 2 * t4q;
            *(float2*)&Out[rbase * OUTROW + c]       = make_float2(acc[mt][nt][0], acc[mt][nt][1]);
            *(float2*)&Out[(rbase + 8) * OUTROW + c] = make_float2(acc[mt][nt][2], acc[mt][nt][3]);
        }
    }
    // ---- Bias into Obc (float4, OROW=128 keeps alignment; row-wise access only)
    #pragma unroll
    for (int it = 0; it < 8; ++it) {
        int q = it * NT_GEMM + tid;
        int r = q >> 5, c4 = (q & 31) * 4;
        *(float4*)&Obc[r * OROW + c4] = *(const float4*)&s_bs[c4];
    }
    __syncthreads();
    // ---- Sparse LOO corrections (warp-owned rows: (lr & 7) == wid)
    for (int d = 0; d < D; ++d) {
        int lr = s_am[d] - row0;
        if ((unsigned)lr < (unsigned)BM && (lr & 7) == wid) {
            float dv = s_dv[d];
            const float* wr = W + wboff + d;
            #pragma unroll
            for (int c = lane; c < D; c += 32)
                Obc[lr * OROW + c] += dv * wr[(size_t)c * H];
        }
    }
    __syncthreads();

    // ---- Final coalesced store
    float* yb = y + ((size_t)n * L + row0) * D;
    #pragma unroll
    for (int it = 0; it < 8; ++it) {
        int q = it * NT_GEMM + tid;
        int r = q >> 5, c4 = (q & 31) * 4;
        float4 v = *(const float4*)&Out[r * OUTROW + c4];
        v.x += Obc[r * OROW + c4];
        v.y += Obc[r * OROW + c4 + 1];
        v.z += Obc[r * OROW + c4 + 2];
        v.w += Obc[r * OROW + c4 + 3];
        *(float4*)&yb[(size_t)r * D + c4] = v;
    }
}

// ---------------------------------------------------------------------------
extern "C" void kernel_launch(void* const* d_in, const int* in_sizes, int n_in,
                              void* d_out, int out_size) {
    (void)in_sizes; (void)n_in; (void)out_size;
    const float* x0 = (const float*)d_in[0];
    const float* x1 = (const float*)d_in[1];
    const float* W0 = (const float*)d_in[2];
    const float* b0 = (const float*)d_in[3];
    const float* W1 = (const float*)d_in[4];
    const float* b1 = (const float*)d_in[5];
    float* y = (float*)d_out;

    cudaFuncSetAttribute(gemm_mma, cudaFuncAttributeMaxDynamicSharedMemorySize, SMEM_TC);

    reduce_partial<<<dim3(CH0 + CH1, N_B), 128>>>(x0, x1);
    merge_kernel<<<dim3(N_B, 2), 128>>>();
    base_kernel<<<dim3(N_B, 2), 512>>>(W0, b0, W1, b1);
    gemm_mma<<<NBLK0 + NBLK1, NT_GEMM, SMEM_TC>>>(x0, x1, W0, W1, y);
}

// round 15
// speedup vs baseline: 1.1134x; 1.0696x over previous
#include <cuda_runtime.h>
#include <cuda_fp16.h>
#include <math.h>
#include <stdint.h>

#define N_B 16
#define D 128
#define L0 2048
#define L1 1024
#define H 384
#define CHUNK 32
#define CH0 (L0/CHUNK)   // 64
#define CH1 (L1/CHUNK)   // 32

#define BM 64
#define NBLK0 (N_B*(L0/BM))  // 512
#define NBLK1 (N_B*(L1/BM))  // 256
#define OROW 128
#define OUTROW 132
#define NT_GEMM 256

// Dynamic smem layout (bytes). Total 73728 -> 3 blocks/SM (216KB).
#define SO_AM   64                    // 128 ints
#define SO_DV   576                   // 128 floats
#define SO_BS   1088                  // 128 floats
#define SO_AF   4096                  // A frags fp16: hi 16KB + lo 16KB
#define A_LO_W  4096                  // word offset of A lo (16KB/4)
#define SO_OBC  40960                 // epilogue bias+corr [64][128] f32 (32KB)
#define SMEM_TC 73728                 // Out[64][132] overlays A at 4096 (33.8KB)

// Scratch (device globals; no allocation allowed)
__device__ float g_pm1[2][N_B][CH0][D];
__device__ float g_pm2[2][N_B][CH0][D];
__device__ int   g_pam[2][N_B][CH0][D];
__device__ float g_top1[2][N_B][D];
__device__ float g_delta[2][N_B][D];
__device__ int   g_amax[2][N_B][D];
__device__ float g_base[2][N_B][D];
// Pre-baked fp16 B fragments of W[:, 0:128]: [g][ks][nt][lane] -> {b0, b1}
__device__ uint2 g_wfragB[2][8][16][32];

// ---------------------------------------------------------------------------
__device__ __forceinline__ void mma_f16(float* d, const uint32_t* a, const uint32_t* b) {
    asm volatile(
        "mma.sync.aligned.m16n8k16.row.col.f32.f16.f16.f32 "
        "{%0,%1,%2,%3}, {%4,%5,%6,%7}, {%8,%9}, {%0,%1,%2,%3};\n"
        : "+f"(d[0]), "+f"(d[1]), "+f"(d[2]), "+f"(d[3])
        : "r"(a[0]), "r"(a[1]), "r"(a[2]), "r"(a[3]), "r"(b[0]), "r"(b[1]));
}

// fp16 hi/lo split of a float2 (hi = rn(v); lo = rn(v - float(hi)))
__device__ __forceinline__ void split2h(float2 v, uint32_t& hi, uint32_t& lo) {
    __half2 h = __float22half2_rn(v);
    float2 hf = __half22float2(h);
    __half2 l = __float22half2_rn(make_float2(v.x - hf.x, v.y - hf.y));
    hi = *(uint32_t*)&h;
    lo = *(uint32_t*)&l;
}

// ---------------------------------------------------------------------------
// Stage 0: bake W[:, 0:128] into fp16 B fragments (once per launch; tiny).
// 8192 lanes: idx -> (g, ks, nt, lane).
// ---------------------------------------------------------------------------
__global__ void prep_w(const float* __restrict__ W0, const float* __restrict__ W1) {
    int idx = blockIdx.x * 256 + threadIdx.x;     // 0..8191
    int lane = idx & 31, tile = idx >> 5;         // tile 0..255
    int g = tile >> 7, t2 = tile & 127;
    int ks = t2 >> 4, nt = t2 & 15;
    const float* W = g ? W1 : W0;
    int o = nt * 8 + (lane >> 2), t4 = lane & 3;
    int kb = ks * 16 + 2 * t4;
    const float* base = W + (size_t)o * H + kb;
    __half2 h0 = __float22half2_rn(*(const float2*)base);
    __half2 h1 = __float22half2_rn(*(const float2*)(base + 8));
    g_wfragB[g][ks][nt][lane] = make_uint2(*(uint32_t*)&h0, *(uint32_t*)&h1);
}

// ---------------------------------------------------------------------------
// Stage 1: per-chunk (32 rows) top2 + argmax. 1536 blocks x 128 thr.
// ---------------------------------------------------------------------------
__global__ void reduce_partial(const float* __restrict__ x0,
                               const float* __restrict__ x1) {
    int n = blockIdx.y, c = blockIdx.x, d = threadIdx.x;
    int g, chunk, L;
    const float* x;
    if (c < CH0) { g = 0; chunk = c;       L = L0; x = x0; }
    else         { g = 1; chunk = c - CH0; L = L1; x = x1; }
    const float* p = x + ((size_t)n * L + (size_t)chunk * CHUNK) * D + d;
    float m1 = -INFINITY, m2 = -INFINITY;
    int am = 0;
    #pragma unroll
    for (int r0 = 0; r0 < CHUNK; r0 += 8) {
        float v[8];
        #pragma unroll
        for (int u = 0; u < 8; ++u) v[u] = p[(size_t)(r0 + u) * D];
        #pragma unroll
        for (int u = 0; u < 8; ++u) {
            if (v[u] > m1) { m2 = m1; m1 = v[u]; am = chunk * CHUNK + r0 + u; }
            else if (v[u] > m2) { m2 = v[u]; }
        }
    }
    g_pm1[g][n][chunk][d] = m1;
    g_pm2[g][n][chunk][d] = m2;
    g_pam[g][n][chunk][d] = am;
}

// ---------------------------------------------------------------------------
// Stage 2: merge partials -> top1 / (top2-top1) / argmax. Grid (16, 2).
// ---------------------------------------------------------------------------
__global__ void merge_kernel() {
    int n = blockIdx.x, g = blockIdx.y, d = threadIdx.x;
    int CH = g ? CH1 : CH0;
    float m1 = -INFINITY, m2 = -INFINITY;
    int am = 0;
    for (int c0 = 0; c0 < CH; c0 += 4) {
        float p1[4], p2[4]; int pa[4];
        #pragma unroll
        for (int u = 0; u < 4; ++u) {
            p1[u] = g_pm1[g][n][c0 + u][d];
            p2[u] = g_pm2[g][n][c0 + u][d];
            pa[u] = g_pam[g][n][c0 + u][d];
        }
        #pragma unroll
        for (int u = 0; u < 4; ++u) {
            if (p1[u] > m1) { m2 = fmaxf(m1, p2[u]); m1 = p1[u]; am = pa[u]; }
            else            { m2 = fmaxf(m2, p1[u]); }
        }
    }
    g_top1[g][n][d]  = m1;
    g_delta[g][n][d] = m2 - m1;
    g_amax[g][n][d]  = am;
}

// ---------------------------------------------------------------------------
// Stage 3: base bias. Grid (16, 2), 512 thr.
// ---------------------------------------------------------------------------
__global__ void base_kernel(const float* __restrict__ W0, const float* __restrict__ b0,
                            const float* __restrict__ W1, const float* __restrict__ b1) {
    int n = blockIdx.x, g = blockIdx.y;
    const float* W = g ? W1 : W0;
    const float* b = g ? b1 : b0;
    int tid = threadIdx.x;
    __shared__ float tv[2 * D];
    if (tid < D)          tv[tid] = g_top1[0][n][tid];
    else if (tid < 2 * D) tv[tid] = g_top1[1][n][tid - D];
    __syncthreads();
    int lane = tid & 31, w = tid >> 5;   // 16 warps
    #pragma unroll
    for (int oo = 0; oo < 8; ++oo) {
        int o = w + 16 * oo;
        const float* wr = W + (size_t)o * H + D;   // cols 128..383
        float s = 0.0f;
        #pragma unroll
        for (int c = 0; c < 8; ++c) { int dd = lane + 32 * c; s += tv[dd] * wr[dd]; }
        #pragma unroll
        for (int off = 16; off; off >>= 1) s += __shfl_down_sync(0xffffffffu, s, off);
        if (lane == 0) g_base[g][n][o] = s + b[o];
    }
}

// ---------------------------------------------------------------------------
// Stage 4: HMMA GEMM, fp16 2-pass (x_hi*W_hi + x_lo*W_hi). A staged in smem,
// B fragments LDG'd directly from pre-baked global (L1/L2-hot).
// 64x128 tile, 8 warps 2(M)x4(N), 72KB smem -> 3 blocks/SM.
// ---------------------------------------------------------------------------
__global__ void __launch_bounds__(NT_GEMM, 3)
gemm_mma(const float* __restrict__ x0, const float* __restrict__ x1,
         const float* __restrict__ W0, const float* __restrict__ W1,
         float* __restrict__ yout) {
    extern __shared__ char sm[];

    int bid = blockIdx.x;
    int g, n, t, L, wboff;
    const float* x; const float* W; float* y;
    if (bid < NBLK0) {
        g = 0; n = bid >> 5; t = bid & 31; L = L0; wboff = D;
        x = x0; W = W0; y = yout;
    } else {
        int b2 = bid - NBLK0;
        g = 1; n = b2 >> 4; t = b2 & 15; L = L1; wboff = 2 * D;
        x = x1; W = W1; y = yout + (size_t)N_B * L0 * D;
    }
    int row0 = t * BM;
    int tid = threadIdx.x, wid = tid >> 5, lane = tid & 31;

    int*      s_am = (int*)(sm + SO_AM);
    float*    s_dv = (float*)(sm + SO_DV);
    float*    s_bs = (float*)(sm + SO_BS);
    uint32_t* AF   = (uint32_t*)(sm + SO_AF);

    if (tid < D) {
        s_am[tid] = g_amax[g][n][tid];
        s_dv[tid] = g_delta[g][n][tid];
        s_bs[tid] = g_base[g][n][tid];
    }

    // ---- Stage A (64 rows): 32 tiles (8ks x 4mt), fp16 hi/lo uint4 frag/thread.
    const float* xb = x + ((size_t)n * L + row0) * D;
    #pragma unroll
    for (int it = 0; it < 4; ++it) {
        int slot = tid + NT_GEMM * it;       // 1024 slots
        int tile = slot >> 5, ln = slot & 31;
        int ks = tile >> 2, mt = tile & 3;
        int r0 = mt * 16 + (ln >> 2), t4 = ln & 3;
        int kb = ks * 16 + 2 * t4;
        const float* base = xb + (size_t)r0 * D + kb;
        float2 v00 = *(const float2*)(base);
        float2 v10 = *(const float2*)(base + 8 * D);
        float2 v01 = *(const float2*)(base + 8);
        float2 v11 = *(const float2*)(base + 8 * D + 8);
        uint32_t h0, l0, h1, l1, h2, l2, h3, l3;
        split2h(v00, h0, l0); split2h(v10, h1, l1);
        split2h(v01, h2, l2); split2h(v11, h3, l3);
        int widx = tile * 128 + ln * 4;
        *(uint4*)(AF + widx)          = make_uint4(h0, h1, h2, h3);
        *(uint4*)(AF + A_LO_W + widx) = make_uint4(l0, l1, l2, l3);
    }
    __syncthreads();

    // ---- MMA mainloop: 8 ksteps; A from smem, B frags from global.
    int warp_m = wid & 1, warp_n = wid >> 1;
    float acc[2][4][4];
    #pragma unroll
    for (int mt = 0; mt < 2; ++mt)
        #pragma unroll
        for (int nt = 0; nt < 4; ++nt)
            #pragma unroll
            for (int q = 0; q < 4; ++q) acc[mt][nt][q] = 0.0f;

    #pragma unroll
    for (int ks = 0; ks < 8; ++ks) {
        uint32_t ah[2][4], al[2][4], bh[4][2];
        #pragma unroll
        for (int nt = 0; nt < 4; ++nt) {
            uint2 wv = g_wfragB[g][ks][(warp_n << 2) + nt][lane];
            bh[nt][0] = wv.x; bh[nt][1] = wv.y;
        }
        #pragma unroll
        for (int mt = 0; mt < 2; ++mt) {
            const uint32_t* ab = AF + ((ks << 2) + (warp_m << 1) + mt) * 128;
            uint4 vh = ((const uint4*)ab)[lane];
            uint4 vl = ((const uint4*)(ab + A_LO_W))[lane];
            ah[mt][0] = vh.x; ah[mt][1] = vh.y; ah[mt][2] = vh.z; ah[mt][3] = vh.w;
            al[mt][0] = vl.x; al[mt][1] = vl.y; al[mt][2] = vl.z; al[mt][3] = vl.w;
        }
        #pragma unroll
        for (int mt = 0; mt < 2; ++mt)
            #pragma unroll
            for (int nt = 0; nt < 4; ++nt)
                mma_f16(acc[mt][nt], ah[mt], bh[nt]);
        #pragma unroll
        for (int mt = 0; mt < 2; ++mt)
            #pragma unroll
            for (int nt = 0; nt < 4; ++nt)
                mma_f16(acc[mt][nt], al[mt], bh[nt]);
    }
    __syncthreads();   // A frags dead; overlay Out

    // ---- Restage accumulators (Out overlays A region)
    float* Out = (float*)(sm + SO_AF);   // [64][OUTROW]
    float* Obc = (float*)(sm + SO_OBC);  // [64][OROW]
    int gq = lane >> 2, t4q = lane & 3;
    #pragma unroll
    for (int mt = 0; mt < 2; ++mt) {
        int rbase = warp_m * 32 + mt * 16 + gq;
        #pragma unroll
        for (int nt = 0; nt < 4; ++nt) {
            int c = warp_n * 32 + nt * 8 + 2 * t4q;
            *(float2*)&Out[rbase * OUTROW + c]       = make_float2(acc[mt][nt][0], acc[mt][nt][1]);
            *(float2*)&Out[(rbase + 8) * OUTROW + c] = make_float2(acc[mt][nt][2], acc[mt][nt][3]);
        }
    }
    // ---- Bias into Obc
    #pragma unroll
    for (int it = 0; it < 8; ++it) {
        int q = it * NT_GEMM + tid;
        int r = q >> 5, c4 = (q & 31) * 4;
        *(float4*)&Obc[r * OROW + c4] = *(const float4*)&s_bs[c4];
    }
    __syncthreads();
    // ---- Sparse LOO corrections (warp-owned rows: (lr & 7) == wid), fp32 exact
    for (int d = 0; d < D; ++d) {
        int lr = s_am[d] - row0;
        if ((unsigned)lr < (unsigned)BM && (lr & 7) == wid) {
            float dv = s_dv[d];
            const float* wr = W + wboff + d;
            #pragma unroll
            for (int c = lane; c < D; c += 32)
                Obc[lr * OROW + c] += dv * wr[(size_t)c * H];
        }
    }
    __syncthreads();

    // ---- Final coalesced store
    float* yb = y + ((size_t)n * L + row0) * D;
    #pragma unroll
    for (int it = 0; it < 8; ++it) {
        int q = it * NT_GEMM + tid;
        int r = q >> 5, c4 = (q & 31) * 4;
        float4 v = *(const float4*)&Out[r * OUTROW + c4];
        v.x += Obc[r * OROW + c4];
        v.y += Obc[r * OROW + c4 + 1];
        v.z += Obc[r * OROW + c4 + 2];
        v.w += Obc[r * OROW + c4 + 3];
        *(float4*)&yb[(size_t)r * D + c4] = v;
    }
}

// ---------------------------------------------------------------------------
extern "C" void kernel_launch(void* const* d_in, const int* in_sizes, int n_in,
                              void* d_out, int out_size) {
    (void)in_sizes; (void)n_in; (void)out_size;
    const float* x0 = (const float*)d_in[0];
    const float* x1 = (const float*)d_in[1];
    const float* W0 = (const float*)d_in[2];
    const float* b0 = (const float*)d_in[3];
    const float* W1 = (const float*)d_in[4];
    const float* b1 = (const float*)d_in[5];
    float* y = (float*)d_out;

    cudaFuncSetAttribute(gemm_mma, cudaFuncAttributeMaxDynamicSharedMemorySize, SMEM_TC);

    prep_w<<<32, 256>>>(W0, W1);
    reduce_partial<<<dim3(CH0 + CH1, N_B), 128>>>(x0, x1);
    merge_kernel<<<dim3(N_B, 2), 128>>>();
    base_kernel<<<dim3(N_B, 2), 512>>>(W0, b0, W1, b1);
    gemm_mma<<<NBLK0 + NBLK1, NT_GEMM, SMEM_TC>>>(x0, x1, W0, W1, y);
}

// round 16
// speedup vs baseline: 1.1334x; 1.0180x over previous
#include <cuda_runtime.h>
#include <cuda_fp16.h>
#include <math.h>
#include <stdint.h>

#define N_B 16
#define D 128
#define L0 2048
#define L1 1024
#define H 384
#define CHUNK 32
#define CH0 (L0/CHUNK)   // 64
#define CH1 (L1/CHUNK)   // 32

#define BM 64
#define NBLK0 (N_B*(L0/BM))  // 512
#define NBLK1 (N_B*(L1/BM))  // 256
#define OUTROW 132
#define NT_GEMM 256

// Dynamic smem layout (bytes). Total 37888 -> high occupancy.
#define SO_AM   64                    // 128 ints
#define SO_DV   576                   // 128 floats
#define SO_BS   1088                  // 128 floats
#define SO_AF   4096                  // A frags fp16 hi: 16KB; Out overlays (33.8KB)
#define SMEM_TC (4096 + BM * OUTROW * 4)   // 37888

// Scratch (device globals; no allocation allowed)
__device__ float g_pm1[2][N_B][CH0][D];
__device__ float g_pm2[2][N_B][CH0][D];
__device__ int   g_pam[2][N_B][CH0][D];
__device__ float g_top1[2][N_B][D];
__device__ float g_delta[2][N_B][D];
__device__ int   g_amax[2][N_B][D];
__device__ float g_base[2][N_B][D];
// Pre-baked fp16 B fragments of W[:, 0:128]: [g][ks][nt][lane] -> {b0, b1}
__device__ uint2 g_wfragB[2][8][16][32];

// ---------------------------------------------------------------------------
__device__ __forceinline__ void mma_f16(float* d, const uint32_t* a, const uint32_t* b) {
    asm volatile(
        "mma.sync.aligned.m16n8k16.row.col.f32.f16.f16.f32 "
        "{%0,%1,%2,%3}, {%4,%5,%6,%7}, {%8,%9}, {%0,%1,%2,%3};\n"
        : "+f"(d[0]), "+f"(d[1]), "+f"(d[2]), "+f"(d[3])
        : "r"(a[0]), "r"(a[1]), "r"(a[2]), "r"(a[3]), "r"(b[0]), "r"(b[1]));
}

// ---------------------------------------------------------------------------
// Stage 0: bake W[:, 0:128] into fp16 B fragments (once per launch; tiny).
// ---------------------------------------------------------------------------
__global__ void prep_w(const float* __restrict__ W0, const float* __restrict__ W1) {
    int idx = blockIdx.x * 256 + threadIdx.x;     // 0..8191
    int lane = idx & 31, tile = idx >> 5;         // tile 0..255
    int g = tile >> 7, t2 = tile & 127;
    int ks = t2 >> 4, nt = t2 & 15;
    const float* W = g ? W1 : W0;
    int o = nt * 8 + (lane >> 2), t4 = lane & 3;
    int kb = ks * 16 + 2 * t4;
    const float* base = W + (size_t)o * H + kb;
    __half2 h0 = __float22half2_rn(*(const float2*)base);
    __half2 h1 = __float22half2_rn(*(const float2*)(base + 8));
    g_wfragB[g][ks][nt][lane] = make_uint2(*(uint32_t*)&h0, *(uint32_t*)&h1);
}

// ---------------------------------------------------------------------------
// Stage 1: per-chunk (32 rows) top2 + argmax. 1536 blocks x 128 thr.
// ---------------------------------------------------------------------------
__global__ void reduce_partial(const float* __restrict__ x0,
                               const float* __restrict__ x1) {
    int n = blockIdx.y, c = blockIdx.x, d = threadIdx.x;
    int g, chunk, L;
    const float* x;
    if (c < CH0) { g = 0; chunk = c;       L = L0; x = x0; }
    else         { g = 1; chunk = c - CH0; L = L1; x = x1; }
    const float* p = x + ((size_t)n * L + (size_t)chunk * CHUNK) * D + d;
    float m1 = -INFINITY, m2 = -INFINITY;
    int am = 0;
    #pragma unroll
    for (int r0 = 0; r0 < CHUNK; r0 += 8) {
        float v[8];
        #pragma unroll
        for (int u = 0; u < 8; ++u) v[u] = p[(size_t)(r0 + u) * D];
        #pragma unroll
        for (int u = 0; u < 8; ++u) {
            if (v[u] > m1) { m2 = m1; m1 = v[u]; am = chunk * CHUNK + r0 + u; }
            else if (v[u] > m2) { m2 = v[u]; }
        }
    }
    g_pm1[g][n][chunk][d] = m1;
    g_pm2[g][n][chunk][d] = m2;
    g_pam[g][n][chunk][d] = am;
}

// ---------------------------------------------------------------------------
// Stage 2: merge partials -> top1 / (top2-top1) / argmax. Grid (16, 2).
// ---------------------------------------------------------------------------
__global__ void merge_kernel() {
    int n = blockIdx.x, g = blockIdx.y, d = threadIdx.x;
    int CH = g ? CH1 : CH0;
    float m1 = -INFINITY, m2 = -INFINITY;
    int am = 0;
    for (int c0 = 0; c0 < CH; c0 += 4) {
        float p1[4], p2[4]; int pa[4];
        #pragma unroll
        for (int u = 0; u < 4; ++u) {
            p1[u] = g_pm1[g][n][c0 + u][d];
            p2[u] = g_pm2[g][n][c0 + u][d];
            pa[u] = g_pam[g][n][c0 + u][d];
        }
        #pragma unroll
        for (int u = 0; u < 4; ++u) {
            if (p1[u] > m1) { m2 = fmaxf(m1, p2[u]); m1 = p1[u]; am = pa[u]; }
            else            { m2 = fmaxf(m2, p1[u]); }
        }
    }
    g_top1[g][n][d]  = m1;
    g_delta[g][n][d] = m2 - m1;
    g_amax[g][n][d]  = am;
}

// ---------------------------------------------------------------------------
// Stage 3: base bias. Grid (16, 2), 512 thr.
// ---------------------------------------------------------------------------
__global__ void base_kernel(const float* __restrict__ W0, const float* __restrict__ b0,
                            const float* __restrict__ W1, const float* __restrict__ b1) {
    int n = blockIdx.x, g = blockIdx.y;
    const float* W = g ? W1 : W0;
    const float* b = g ? b1 : b0;
    int tid = threadIdx.x;
    __shared__ float tv[2 * D];
    if (tid < D)          tv[tid] = g_top1[0][n][tid];
    else if (tid < 2 * D) tv[tid] = g_top1[1][n][tid - D];
    __syncthreads();
    int lane = tid & 31, w = tid >> 5;   // 16 warps
    #pragma unroll
    for (int oo = 0; oo < 8; ++oo) {
        int o = w + 16 * oo;
        const float* wr = W + (size_t)o * H + D;   // cols 128..383
        float s = 0.0f;
        #pragma unroll
        for (int c = 0; c < 8; ++c) { int dd = lane + 32 * c; s += tv[dd] * wr[dd]; }
        #pragma unroll
        for (int off = 16; off; off >>= 1) s += __shfl_down_sync(0xffffffffu, s, off);
        if (lane == 0) g_base[g][n][o] = s + b[o];
    }
}

// ---------------------------------------------------------------------------
// Stage 4: HMMA GEMM, single-pass fp16 (x_h * W_h); dense-term quantization
// error ~6e-5 rel; bias + sparse LOO corrections applied in exact fp32.
// 64x128 tile, 8 warps 2(M)x4(N); smem 37.9KB -> 3+ blocks/SM.
// ---------------------------------------------------------------------------
__global__ void __launch_bounds__(NT_GEMM, 3)
gemm_mma(const float* __restrict__ x0, const float* __restrict__ x1,
         const float* __restrict__ W0, const float* __restrict__ W1,
         float* __restrict__ yout) {
    extern __shared__ char sm[];

    int bid = blockIdx.x;
    int g, n, t, L, wboff;
    const float* x; const float* W; float* y;
    if (bid < NBLK0) {
        g = 0; n = bid >> 5; t = bid & 31; L = L0; wboff = D;
        x = x0; W = W0; y = yout;
    } else {
        int b2 = bid - NBLK0;
        g = 1; n = b2 >> 4; t = b2 & 15; L = L1; wboff = 2 * D;
        x = x1; W = W1; y = yout + (size_t)N_B * L0 * D;
    }
    int row0 = t * BM;
    int tid = threadIdx.x, wid = tid >> 5, lane = tid & 31;

    int*      s_am = (int*)(sm + SO_AM);
    float*    s_dv = (float*)(sm + SO_DV);
    float*    s_bs = (float*)(sm + SO_BS);
    uint32_t* AF   = (uint32_t*)(sm + SO_AF);

    if (tid < D) {
        s_am[tid] = g_amax[g][n][tid];
        s_dv[tid] = g_delta[g][n][tid];
        s_bs[tid] = g_base[g][n][tid];
    }

    // ---- Stage A (64 rows): 32 tiles (8ks x 4mt), fp16 hi uint4 frag/thread.
    const float* xb = x + ((size_t)n * L + row0) * D;
    #pragma unroll
    for (int it = 0; it < 4; ++it) {
        int slot = tid + NT_GEMM * it;       // 1024 slots
        int tile = slot >> 5, ln = slot & 31;
        int ks = tile >> 2, mt = tile & 3;
        int r0 = mt * 16 + (ln >> 2), t4 = ln & 3;
        int kb = ks * 16 + 2 * t4;
        const float* base = xb + (size_t)r0 * D + kb;
        __half2 h0 = __float22half2_rn(*(const float2*)(base));
        __half2 h1 = __float22half2_rn(*(const float2*)(base + 8 * D));
        __half2 h2 = __float22half2_rn(*(const float2*)(base + 8));
        __half2 h3 = __float22half2_rn(*(const float2*)(base + 8 * D + 8));
        *(uint4*)(AF + tile * 128 + ln * 4) =
            make_uint4(*(uint32_t*)&h0, *(uint32_t*)&h1, *(uint32_t*)&h2, *(uint32_t*)&h3);
    }
    __syncthreads();

    // ---- MMA mainloop: 8 ksteps; A from smem, B frags from global (L1/L2-hot).
    int warp_m = wid & 1, warp_n = wid >> 1;
    float acc[2][4][4];
    #pragma unroll
    for (int mt = 0; mt < 2; ++mt)
        #pragma unroll
        for (int nt = 0; nt < 4; ++nt)
            #pragma unroll
            for (int q = 0; q < 4; ++q) acc[mt][nt][q] = 0.0f;

    #pragma unroll
    for (int ks = 0; ks < 8; ++ks) {
        uint32_t ah[2][4], bh[4][2];
        #pragma unroll
        for (int nt = 0; nt < 4; ++nt) {
            uint2 wv = g_wfragB[g][ks][(warp_n << 2) + nt][lane];
            bh[nt][0] = wv.x; bh[nt][1] = wv.y;
        }
        #pragma unroll
        for (int mt = 0; mt < 2; ++mt) {
            uint4 vh = ((const uint4*)(AF + ((ks << 2) + (warp_m << 1) + mt) * 128))[lane];
            ah[mt][0] = vh.x; ah[mt][1] = vh.y; ah[mt][2] = vh.z; ah[mt][3] = vh.w;
        }
        #pragma unroll
        for (int mt = 0; mt < 2; ++mt)
            #pragma unroll
            for (int nt = 0; nt < 4; ++nt)
                mma_f16(acc[mt][nt], ah[mt], bh[nt]);
    }
    __syncthreads();   // A frags dead; overlay Out

    // ---- Restage accumulators (Out overlays A region)
    float* Out = (float*)(sm + SO_AF);   // [64][OUTROW]
    int gq = lane >> 2, t4q = lane & 3;
    #pragma unroll
    for (int mt = 0; mt < 2; ++mt) {
        int rbase = warp_m * 32 + mt * 16 + gq;
        #pragma unroll
        for (int nt = 0; nt < 4; ++nt) {
            int c = warp_n * 32 + nt * 8 + 2 * t4q;
            *(float2*)&Out[rbase * OUTROW + c]       = make_float2(acc[mt][nt][0], acc[mt][nt][1]);
            *(float2*)&Out[(rbase + 8) * OUTROW + c] = make_float2(acc[mt][nt][2], acc[mt][nt][3]);
        }
    }
    __syncthreads();

    // ---- Sparse LOO corrections directly into Out (warp-owned rows), fp32 exact
    for (int d = 0; d < D; ++d) {
        int lr = s_am[d] - row0;
        if ((unsigned)lr < (unsigned)BM && (lr & 7) == wid) {
            float dv = s_dv[d];
            const float* wr = W + wboff + d;
            #pragma unroll
            for (int c = lane; c < D; c += 32)
                Out[lr * OUTROW + c] += dv * wr[(size_t)c * H];
        }
    }
    __syncthreads();

    // ---- Final coalesced store: Out + bias
    float* yb = y + ((size_t)n * L + row0) * D;
    #pragma unroll
    for (int it = 0; it < 8; ++it) {
        int q = it * NT_GEMM + tid;
        int r = q >> 5, c4 = (q & 31) * 4;
        float4 v = *(const float4*)&Out[r * OUTROW + c4];
        float4 bz = *(const float4*)&s_bs[c4];
        v.x += bz.x; v.y += bz.y; v.z += bz.z; v.w += bz.w;
        *(float4*)&yb[(size_t)r * D + c4] = v;
    }
}

// ---------------------------------------------------------------------------
extern "C" void kernel_launch(void* const* d_in, const int* in_sizes, int n_in,
                              void* d_out, int out_size) {
    (void)in_sizes; (void)n_in; (void)out_size;
    const float* x0 = (const float*)d_in[0];
    const float* x1 = (const float*)d_in[1];
    const float* W0 = (const float*)d_in[2];
    const float* b0 = (const float*)d_in[3];
    const float* W1 = (const float*)d_in[4];
    const float* b1 = (const float*)d_in[5];
    float* y = (float*)d_out;

    cudaFuncSetAttribute(gemm_mma, cudaFuncAttributeMaxDynamicSharedMemorySize, SMEM_TC);

    prep_w<<<32, 256>>>(W0, W1);
    reduce_partial<<<dim3(CH0 + CH1, N_B), 128>>>(x0, x1);
    merge_kernel<<<dim3(N_B, 2), 128>>>();
    base_kernel<<<dim3(N_B, 2), 512>>>(W0, b0, W1, b1);
    gemm_mma<<<NBLK0 + NBLK1, NT_GEMM, SMEM_TC>>>(x0, x1, W0, W1, y);
}

// round 17
// speedup vs baseline: 2.1012x; 1.8539x over previous
#include <cuda_runtime.h>
#include <cuda_fp16.h>
#include <math.h>
#include <stdint.h>

#define N_B 16
#define D 128
#define L0 2048
#define L1 1024
#define H 384
#define CHUNK 32
#define CH0 (L0/CHUNK)   // 64
#define CH1 (L1/CHUNK)   // 32

#define BM 64
#define NBLK0 (N_B*(L0/BM))  // 512
#define NBLK1 (N_B*(L1/BM))  // 256
#define AROW 136             // fp16 row stride (272B -> +4 banks/row, LDSM-safe)
#define OUTROW 132
#define NT_GEMM 256

// Dynamic smem layout (bytes). Total 55296 -> 4 blocks/SM.
#define SO_AM   64                    // 128 ints
#define SO_DV   576                   // 128 floats
#define SO_BS   1088                  // 128 floats
#define SO_A    4096                  // fp16 A [64][AROW] = 17408
#define SO_OUT  21504                 // f32 Out [64][OUTROW] = 33792
#define SMEM_TC 55296

// Scratch (device globals; no allocation allowed)
__device__ float g_pm1[2][N_B][CH0][D];
__device__ float g_pm2[2][N_B][CH0][D];
__device__ int   g_pam[2][N_B][CH0][D];
__device__ float g_top1[2][N_B][D];
__device__ float g_delta[2][N_B][D];
__device__ int   g_amax[2][N_B][D];
__device__ float g_base[2][N_B][D];
// Pre-baked fp16 B fragments of W[:, 0:128]: [g][ks][nt][lane] -> {b0, b1}
__device__ uint2 g_wfragB[2][8][16][32];

// ---------------------------------------------------------------------------
__device__ __forceinline__ void mma_f16(float* d, const uint32_t* a, const uint32_t* b) {
    asm volatile(
        "mma.sync.aligned.m16n8k16.row.col.f32.f16.f16.f32 "
        "{%0,%1,%2,%3}, {%4,%5,%6,%7}, {%8,%9}, {%0,%1,%2,%3};\n"
        : "+f"(d[0]), "+f"(d[1]), "+f"(d[2]), "+f"(d[3])
        : "r"(a[0]), "r"(a[1]), "r"(a[2]), "r"(a[3]), "r"(b[0]), "r"(b[1]));
}
__device__ __forceinline__ uint32_t smem_u32(const void* p) {
    uint32_t a;
    asm("{ .reg .u64 t; cvta.to.shared.u64 t, %1; cvt.u32.u64 %0, t; }"
        : "=r"(a) : "l"(p));
    return a;
}
__device__ __forceinline__ void ldsm_x4(uint32_t* r, uint32_t addr) {
    asm volatile("ldmatrix.sync.aligned.m8n8.x4.shared.b16 {%0,%1,%2,%3}, [%4];"
                 : "=r"(r[0]), "=r"(r[1]), "=r"(r[2]), "=r"(r[3]) : "r"(addr));
}

// ---------------------------------------------------------------------------
// Stage 0: bake W[:, 0:128] into fp16 B fragments (once per launch; tiny).
// ---------------------------------------------------------------------------
__global__ void prep_w(const float* __restrict__ W0, const float* __restrict__ W1) {
    int idx = blockIdx.x * 256 + threadIdx.x;     // 0..8191
    int lane = idx & 31, tile = idx >> 5;         // tile 0..255
    int g = tile >> 7, t2 = tile & 127;
    int ks = t2 >> 4, nt = t2 & 15;
    const float* W = g ? W1 : W0;
    int o = nt * 8 + (lane >> 2), t4 = lane & 3;
    int kb = ks * 16 + 2 * t4;
    const float* base = W + (size_t)o * H + kb;
    __half2 h0 = __float22half2_rn(*(const float2*)base);
    __half2 h1 = __float22half2_rn(*(const float2*)(base + 8));
    g_wfragB[g][ks][nt][lane] = make_uint2(*(uint32_t*)&h0, *(uint32_t*)&h1);
}

// ---------------------------------------------------------------------------
// Stage 1: per-chunk (32 rows) top2 + argmax. 1536 blocks x 128 thr.
// ---------------------------------------------------------------------------
__global__ void reduce_partial(const float* __restrict__ x0,
                               const float* __restrict__ x1) {
    int n = blockIdx.y, c = blockIdx.x, d = threadIdx.x;
    int g, chunk, L;
    const float* x;
    if (c < CH0) { g = 0; chunk = c;       L = L0; x = x0; }
    else         { g = 1; chunk = c - CH0; L = L1; x = x1; }
    const float* p = x + ((size_t)n * L + (size_t)chunk * CHUNK) * D + d;
    float m1 = -INFINITY, m2 = -INFINITY;
    int am = 0;
    #pragma unroll
    for (int r0 = 0; r0 < CHUNK; r0 += 8) {
        float v[8];
        #pragma unroll
        for (int u = 0; u < 8; ++u) v[u] = p[(size_t)(r0 + u) * D];
        #pragma unroll
        for (int u = 0; u < 8; ++u) {
            if (v[u] > m1) { m2 = m1; m1 = v[u]; am = chunk * CHUNK + r0 + u; }
            else if (v[u] > m2) { m2 = v[u]; }
        }
    }
    g_pm1[g][n][chunk][d] = m1;
    g_pm2[g][n][chunk][d] = m2;
    g_pam[g][n][chunk][d] = am;
}

// ---------------------------------------------------------------------------
// Stage 2: merge partials -> top1 / (top2-top1) / argmax. Grid (16, 2).
// ---------------------------------------------------------------------------
__global__ void merge_kernel() {
    int n = blockIdx.x, g = blockIdx.y, d = threadIdx.x;
    int CH = g ? CH1 : CH0;
    float m1 = -INFINITY, m2 = -INFINITY;
    int am = 0;
    for (int c0 = 0; c0 < CH; c0 += 4) {
        float p1[4], p2[4]; int pa[4];
        #pragma unroll
        for (int u = 0; u < 4; ++u) {
            p1[u] = g_pm1[g][n][c0 + u][d];
            p2[u] = g_pm2[g][n][c0 + u][d];
            pa[u] = g_pam[g][n][c0 + u][d];
        }
        #pragma unroll
        for (int u = 0; u < 4; ++u) {
            if (p1[u] > m1) { m2 = fmaxf(m1, p2[u]); m1 = p1[u]; am = pa[u]; }
            else            { m2 = fmaxf(m2, p1[u]); }
        }
    }
    g_top1[g][n][d]  = m1;
    g_delta[g][n][d] = m2 - m1;
    g_amax[g][n][d]  = am;
}

// ---------------------------------------------------------------------------
// Stage 3: base bias. Grid (2, 16) = (g, o-chunk of 8). W rows in registers,
// n-loop inside (W read ONCE per o instead of per (n,o)).
// ---------------------------------------------------------------------------
__global__ void base_kernel(const float* __restrict__ W0, const float* __restrict__ b0,
                            const float* __restrict__ W1, const float* __restrict__ b1) {
    int g = blockIdx.x, oc = blockIdx.y;
    const float* W = g ? W1 : W0;
    const float* b = g ? b1 : b0;
    int tid = threadIdx.x, lane = tid & 31, w = tid >> 5;   // 8 warps
    __shared__ float tv[N_B][2 * D];   // 32KB: [n][top1_g0 | top1_g1]

    // coalesced load of all top1 vectors
    for (int i = tid; i < N_B * 2 * D; i += 256) {
        int n = i >> 8, dd = i & 255;
        tv[n][dd] = (dd < D) ? g_top1[0][n][dd] : g_top1[1][n][dd - D];
    }
    __syncthreads();

    int o = oc * 8 + w;
    const float* wr = W + (size_t)o * H + D;   // cols 128..383 (len 256)
    float wreg[8];
    #pragma unroll
    for (int c = 0; c < 8; ++c) wreg[c] = wr[lane + 32 * c];
    float bo = b[o];

    #pragma unroll
    for (int n = 0; n < N_B; ++n) {
        float s = 0.0f;
        #pragma unroll
        for (int c = 0; c < 8; ++c) s += wreg[c] * tv[n][lane + 32 * c];
        #pragma unroll
        for (int off = 16; off; off >>= 1) s += __shfl_down_sync(0xffffffffu, s, off);
        if (lane == 0) g_base[g][n][o] = s + bo;
    }
}

// ---------------------------------------------------------------------------
// Stage 4: HMMA GEMM, single-pass fp16. A: coalesced row-major smem + ldmatrix.
// B: pre-baked global fragments. Corrections: ballot-compacted, deterministic.
// 64x128 tile, 8 warps 2(M)x4(N), 55KB smem -> 4 blocks/SM.
// ---------------------------------------------------------------------------
__global__ void __launch_bounds__(NT_GEMM, 4)
gemm_mma(const float* __restrict__ x0, const float* __restrict__ x1,
         const float* __restrict__ W0, const float* __restrict__ W1,
         float* __restrict__ yout) {
    extern __shared__ char sm[];

    int bid = blockIdx.x;
    int g, n, t, L, wboff;
    const float* x; const float* W; float* y;
    if (bid < NBLK0) {
        g = 0; n = bid >> 5; t = bid & 31; L = L0; wboff = D;
        x = x0; W = W0; y = yout;
    } else {
        int b2 = bid - NBLK0;
        g = 1; n = b2 >> 4; t = b2 & 15; L = L1; wboff = 2 * D;
        x = x1; W = W1; y = yout + (size_t)N_B * L0 * D;
    }
    int row0 = t * BM;
    int tid = threadIdx.x, wid = tid >> 5, lane = tid & 31;

    int*    s_am = (int*)(sm + SO_AM);
    float*  s_dv = (float*)(sm + SO_DV);
    float*  s_bs = (float*)(sm + SO_BS);
    __half* As   = (__half*)(sm + SO_A);
    float*  Out  = (float*)(sm + SO_OUT);
    uint32_t As_b = smem_u32(As);

    if (tid < D) {
        s_am[tid] = g_amax[g][n][tid];
        s_dv[tid] = g_delta[g][n][tid];
        s_bs[tid] = g_base[g][n][tid];
    }

    // ---- Stage A: coalesced LDG.128 -> fp16 -> contiguous STS.64 (row-major)
    const float* xb = x + ((size_t)n * L + row0) * D;
    #pragma unroll
    for (int it = 0; it < 8; ++it) {
        int idx = tid + NT_GEMM * it;        // 2048 float4-groups
        int r = idx >> 5, cq = (idx & 31) * 4;
        float4 v = *(const float4*)(xb + (size_t)r * D + cq);
        __half2 ha = __float22half2_rn(make_float2(v.x, v.y));
        __half2 hb = __float22half2_rn(make_float2(v.z, v.w));
        *(uint2*)(As + r * AROW + cq) = make_uint2(*(uint32_t*)&ha, *(uint32_t*)&hb);
    }
    __syncthreads();

    // ---- MMA mainloop: A via ldmatrix.x4 (conflict-free w/ 272B row stride)
    int warp_m = wid & 1, warp_n = wid >> 1;
    float acc[2][4][4];
    #pragma unroll
    for (int mt = 0; mt < 2; ++mt)
        #pragma unroll
        for (int nt = 0; nt < 4; ++nt)
            #pragma unroll
            for (int q = 0; q < 4; ++q) acc[mt][nt][q] = 0.0f;

    int jq = lane >> 3, q8 = lane & 7;       // matrix idx, row-in-matrix
    #pragma unroll
    for (int ks = 0; ks < 8; ++ks) {
        uint32_t bh[4][2];
        #pragma unroll
        for (int nt = 0; nt < 4; ++nt) {
            uint2 wv = g_wfragB[g][ks][(warp_n << 2) + nt][lane];
            bh[nt][0] = wv.x; bh[nt][1] = wv.y;
        }
        #pragma unroll
        for (int mt = 0; mt < 2; ++mt) {
            int row = warp_m * 32 + mt * 16 + (jq & 1) * 8 + q8;
            int col = ks * 16 + (jq >> 1) * 8;
            uint32_t ah[4];
            ldsm_x4(ah, As_b + (uint32_t)(row * AROW + col) * 2);
            #pragma unroll
            for (int nt = 0; nt < 4; ++nt)
                mma_f16(acc[mt][nt], ah, bh[nt]);
        }
    }
    __syncthreads();

    // ---- Restage accumulators into Out
    int gq = lane >> 2, t4q = lane & 3;
    #pragma unroll
    for (int mt = 0; mt < 2; ++mt) {
        int rbase = warp_m * 32 + mt * 16 + gq;
        #pragma unroll
        for (int nt = 0; nt < 4; ++nt) {
            int c = warp_n * 32 + nt * 8 + 2 * t4q;
            *(float2*)&Out[rbase * OUTROW + c]       = make_float2(acc[mt][nt][0], acc[mt][nt][1]);
            *(float2*)&Out[(rbase + 8) * OUTROW + c] = make_float2(acc[mt][nt][2], acc[mt][nt][3]);
        }
    }
    __syncthreads();

    // ---- Sparse LOO corrections: ballot-compacted, warp-owned rows (lr&7)==wid.
    // Deterministic: rounds ascending, ffs ascending; row -> unique warp.
    #pragma unroll
    for (int rnd = 0; rnd < 4; ++rnd) {
        int d = rnd * 32 + lane;
        int lr = s_am[d] - row0;
        bool ok = ((unsigned)lr < (unsigned)BM) && ((lr & 7) == wid);
        unsigned mask = __ballot_sync(0xffffffffu, ok);
        while (mask) {
            int i = __ffs(mask) - 1;
            mask &= mask - 1;
            int lr_i = __shfl_sync(0xffffffffu, lr, i);
            int d_i = rnd * 32 + i;
            float dv = s_dv[d_i];
            const float* wr = W + wboff + d_i;
            #pragma unroll
            for (int cc = 0; cc < 4; ++cc) {
                int c = lane + 32 * cc;
                Out[lr_i * OUTROW + c] += dv * wr[(size_t)c * H];
            }
        }
    }
    __syncthreads();

    // ---- Final coalesced store: Out + bias
    float* yb = y + ((size_t)n * L + row0) * D;
    #pragma unroll
    for (int it = 0; it < 8; ++it) {
        int idx = it * NT_GEMM + tid;
        int r = idx >> 5, c4 = (idx & 31) * 4;
        float4 v = *(const float4*)&Out[r * OUTROW + c4];
        float4 bz = *(const float4*)&s_bs[c4];
        v.x += bz.x; v.y += bz.y; v.z += bz.z; v.w += bz.w;
        *(float4*)&yb[(size_t)r * D + c4] = v;
    }
}

// ---------------------------------------------------------------------------
extern "C" void kernel_launch(void* const* d_in, const int* in_sizes, int n_in,
                              void* d_out, int out_size) {
    (void)in_sizes; (void)n_in; (void)out_size;
    const float* x0 = (const float*)d_in[0];
    const float* x1 = (const float*)d_in[1];
    const float* W0 = (const float*)d_in[2];
    const float* b0 = (const float*)d_in[3];
    const float* W1 = (const float*)d_in[4];
    const float* b1 = (const float*)d_in[5];
    float* y = (float*)d_out;

    cudaFuncSetAttribute(gemm_mma, cudaFuncAttributeMaxDynamicSharedMemorySize, SMEM_TC);

    prep_w<<<32, 256>>>(W0, W1);
    reduce_partial<<<dim3(CH0 + CH1, N_B), 128>>>(x0, x1);
    merge_kernel<<<dim3(N_B, 2), 128>>>();
    base_kernel<<<dim3(2, N_B), 256>>>(W0, b0, W1, b1);
    gemm_mma<<<NBLK0 + NBLK1, NT_GEMM, SMEM_TC>>>(x0, x1, W0, W1, y);
}